// round 3
// baseline (speedup 1.0000x reference)
#include <cuda_runtime.h>

// RankingLoss: B=16384 rows, C=1000 classes. Warp-per-row, no block barriers.
// per row: label = argmax(target); x1 = logits[label];
//   loss = (label==0) ? 0 : sum_{j>=1} relu(l[j]-x1+|label-j|/999) + relu(l[0]-x1+1)
// out = mean over rows.

#define C_CLASSES 1000
#define C4        250           // float4 vecs per row
#define SLOTS     8             // ceil(250/32)
#define WARPS_PB  4
#define THREADS   (WARPS_PB * 32)

__global__ __launch_bounds__(THREADS)
void ranking_loss_kernel(const float* __restrict__ logits,
                         const float* __restrict__ target,
                         float* __restrict__ out,
                         float inv_B) {
    const int warp_id = blockIdx.x * WARPS_PB + (threadIdx.x >> 5);  // row index
    const int lane    = threadIdx.x & 31;

    const float4* trow = reinterpret_cast<const float4*>(target) + (size_t)warp_id * C4;
    const float4* lrow = reinterpret_cast<const float4*>(logits) + (size_t)warp_id * C4;

    // ---- load all slots up front (MLP = 16 LDG.128 per lane), streaming hint ----
    float4 tv[SLOTS], lv[SLOTS];
    #pragma unroll
    for (int s = 0; s < SLOTS; s++) {
        const int v = s * 32 + lane;
        if (v < C4) {
            tv[s] = __ldcs(&trow[v]);
            lv[s] = __ldcs(&lrow[v]);
        } else {
            tv[s] = make_float4(-1.f, -1.f, -1.f, -1.f);     // below uniform[0,1)
            lv[s] = make_float4(-1e30f, -1e30f, -1e30f, -1e30f); // relu -> 0
        }
    }

    // ---- local argmax (ascending index order per lane; strict > keeps first) ----
    // carries the paired logit so x1 needs no reload / dynamic register index
    float m   = tv[0].x;
    int   mi  = lane * 4;
    float mlx = lv[0].x;
    #pragma unroll
    for (int s = 0; s < SLOTS; s++) {
        const int base = (s * 32 + lane) * 4;
        const float tva[4] = {tv[s].x, tv[s].y, tv[s].z, tv[s].w};
        const float lva[4] = {lv[s].x, lv[s].y, lv[s].z, lv[s].w};
        #pragma unroll
        for (int k = 0; k < 4; k++) {
            if (s == 0 && k == 0) continue;
            if (tva[k] > m) { m = tva[k]; mi = base + k; mlx = lva[k]; }
        }
    }

    // ---- warp argmax via REDUX (targets are uniform[0,1) >= 0: positive-float
    //      bit pattern is order-preserving as u32) ----
    const unsigned full = 0xffffffffu;
    const unsigned mb   = __float_as_uint(m);
    const unsigned wmb  = __reduce_max_sync(full, mb);
    const unsigned cand = (mb == wmb) ? (unsigned)mi : 0xffffffffu;
    const unsigned wmi  = __reduce_min_sync(full, cand);       // first-index tiebreak

    const int label = (int)wmi;
    if (label == 0) return;                                    // row contributes 0

    // owner lane broadcasts its carried logit
    const unsigned own = __ballot_sync(full, (mb == wmb) & ((unsigned)mi == wmi));
    const float x1 = __shfl_sync(full, mlx, __ffs(own) - 1);

    // ---- margin-relu sum ----
    const float inv_pos = 1.0f / (float)(C_CLASSES - 1);
    const float flabel  = (float)label;
    const float nx1     = -x1;

    float sum = 0.f;
    #pragma unroll
    for (int s = 0; s < SLOTS; s++) {
        const float fb = (float)((s * 32 + lane) * 4);
        const float lva[4] = {lv[s].x, lv[s].y, lv[s].z, lv[s].w};
        #pragma unroll
        for (int k = 0; k < 4; k++) {
            float margin;
            if (s == 0 && k == 0)       // element index 4*lane; ==0 only on lane 0
                margin = (lane == 0) ? 1.0f : fabsf(flabel - fb) * inv_pos;
            else
                margin = fabsf(flabel - (fb + (float)k)) * inv_pos;
            sum += fmaxf(0.f, lva[k] + nx1 + margin);
        }
    }

    // ---- warp sum, one atomic per warp ----
    #pragma unroll
    for (int off = 16; off > 0; off >>= 1)
        sum += __shfl_down_sync(full, sum, off);
    if (lane == 0)
        atomicAdd(out, sum * inv_B);
}

extern "C" void kernel_launch(void* const* d_in, const int* in_sizes, int n_in,
                              void* d_out, int out_size) {
    const float* logits = (const float*)d_in[0];
    const float* target = (const float*)d_in[1];
    float* out = (float*)d_out;

    const int B = in_sizes[0] / C_CLASSES;   // 16384

    cudaMemsetAsync(out, 0, sizeof(float));
    ranking_loss_kernel<<<B / WARPS_PB, THREADS>>>(logits, target, out, 1.0f / (float)B);
}

// round 5
// speedup vs baseline: 1.1937x; 1.1937x over previous
#include <cuda_runtime.h>
#include <cstdint>

// RankingLoss: B=16384 rows, C=1000 classes.
// TMA (cp.async.bulk) staged pipeline: each block streams ROWS_PB rows
// through a STAGES-deep smem ring, consuming with block-wide argmax + margin sum.

#define C_CLASSES 1000
#define C4        250
#define ROW_BYTES 4000          // 1000 floats
#define STAGES    5
#define ROWS_PB   8
#define THREADS   256

__device__ __forceinline__ unsigned su32(const void* p) {
    return (unsigned)__cvta_generic_to_shared(p);
}

__device__ __forceinline__ void bulk_ldg(unsigned dst, const void* src, unsigned mbar) {
    asm volatile(
        "cp.async.bulk.shared::cta.global.mbarrier::complete_tx::bytes [%0], [%1], %2, [%3];"
        :: "r"(dst), "l"(src), "r"(ROW_BYTES), "r"(mbar) : "memory");
}

__device__ __forceinline__ void mbar_wait(unsigned mbar, unsigned phase) {
    unsigned done;
    asm volatile(
        "{\n\t.reg .pred p;\n\t"
        "mbarrier.try_wait.parity.acquire.cta.shared::cta.b64 p, [%1], %2, 0x989680;\n\t"
        "selp.b32 %0, 1, 0, p;\n\t}"
        : "=r"(done) : "r"(mbar), "r"(phase) : "memory");
    while (!done) {
        asm volatile(
            "{\n\t.reg .pred p;\n\t"
            "mbarrier.try_wait.parity.acquire.cta.shared::cta.b64 p, [%1], %2, 0x989680;\n\t"
            "selp.b32 %0, 1, 0, p;\n\t}"
            : "=r"(done) : "r"(mbar), "r"(phase) : "memory");
    }
}

__global__ __launch_bounds__(THREADS)
void ranking_loss_kernel(const float* __restrict__ logits,
                         const float* __restrict__ target,
                         float* __restrict__ out,
                         float inv_B) {
    __shared__ alignas(16) char buf[STAGES][2 * ROW_BYTES];   // [tgt | lgt] per stage
    __shared__ alignas(8) unsigned long long mbar[STAGES];
    __shared__ unsigned s_mb[8], s_mi[8];
    __shared__ float    s_lx[8], s_sum[8];

    const int t    = threadIdx.x;
    const int lane = t & 31;
    const int warp = t >> 5;
    const int row0 = blockIdx.x * ROWS_PB;
    const bool act = (t < C4);

    if (t == 0) {
        #pragma unroll
        for (int s = 0; s < STAGES; s++)
            asm volatile("mbarrier.init.shared.b64 [%0], 1;"
                         :: "r"(su32(&mbar[s])) : "memory");
    }
    __syncthreads();

    // ---- prologue: fill all stages ----
    if (t == 0) {
        #pragma unroll
        for (int s = 0; s < STAGES; s++) {
            const int r = row0 + s;
            const unsigned mb = su32(&mbar[s]);
            asm volatile("mbarrier.arrive.expect_tx.shared.b64 _, [%0], %1;"
                         :: "r"(mb), "r"(2 * ROW_BYTES) : "memory");
            bulk_ldg(su32(buf[s]),             target + (size_t)r * C_CLASSES, mb);
            bulk_ldg(su32(buf[s]) + ROW_BYTES, logits + (size_t)r * C_CLASSES, mb);
        }
    }

    float loss = 0.f;

    for (int r = 0; r < ROWS_PB; r++) {
        const int s = r % STAGES;
        const unsigned phase = (unsigned)(r / STAGES) & 1u;

        mbar_wait(su32(&mbar[s]), phase);

        // ---- consume: load this thread's vec4 from smem (conflict-free LDS.128) ----
        const float4* tv4 = reinterpret_cast<const float4*>(buf[s]);
        const float4* lv4 = reinterpret_cast<const float4*>(buf[s] + ROW_BYTES);
        float4 tv = make_float4(0.f, 0.f, 0.f, 0.f);             // pad: never beats real max
        float4 lv = make_float4(-1e30f, -1e30f, -1e30f, -1e30f); // pad: relu -> 0
        if (act) { tv = tv4[t]; lv = lv4[t]; }

        // ---- local argmax (first-index on ties), carrying the paired logit ----
        const int base = 4 * t;
        float m = tv.x; int mi = base; float mlx = lv.x;
        if (tv.y > m) { m = tv.y; mi = base + 1; mlx = lv.y; }
        if (tv.z > m) { m = tv.z; mi = base + 2; mlx = lv.z; }
        if (tv.w > m) { m = tv.w; mi = base + 3; mlx = lv.w; }

        // targets are uniform[0,1) >= 0: positive-float bits are order-preserving
        const unsigned full = 0xffffffffu;
        const unsigned mb   = __float_as_uint(m);
        const unsigned wmb  = __reduce_max_sync(full, mb);
        const unsigned cand = (mb == wmb) ? (unsigned)mi : 0xffffffffu;
        const unsigned wmi  = __reduce_min_sync(full, cand);

        if (mb == wmb && (unsigned)mi == wmi) s_lx[warp] = mlx;  // unique owner
        if (lane == 0) { s_mb[warp] = wmb; s_mi[warp] = wmi; }
        __syncthreads();

        // ---- every thread scans the 8 warp winners ----
        unsigned bb = s_mb[0]; unsigned bi = s_mi[0]; float x1 = s_lx[0];
        #pragma unroll
        for (int w = 1; w < 8; w++) {
            const unsigned ob = s_mb[w], oi = s_mi[w];
            if (ob > bb || (ob == bb && oi < bi)) { bb = ob; bi = oi; x1 = s_lx[w]; }
        }
        const int label = (int)bi;

        // ---- margin-relu sum ----
        float sum = 0.f;
        if (label != 0) {
            const float inv_pos = 1.0f / (float)(C_CLASSES - 1);
            const float flabel  = (float)label;
            const float nx1     = -x1;
            const float la[4]   = {lv.x, lv.y, lv.z, lv.w};
            const float fb      = (float)base;
            #pragma unroll
            for (int k = 0; k < 4; k++) {
                // j==0 only at t==0,k==0: margin = 1.0 (NEG_MARGIN * relu term)
                const float margin = (t == 0 && k == 0)
                                   ? 1.0f
                                   : fabsf(flabel - (fb + (float)k)) * inv_pos;
                sum += fmaxf(0.f, la[k] + nx1 + margin);
            }
        }

        #pragma unroll
        for (int off = 16; off > 0; off >>= 1)
            sum += __shfl_down_sync(full, sum, off);
        if (lane == 0) s_sum[warp] = sum;
        __syncthreads();   // all smem reads of buf[s] complete past this point

        if (t == 0) {
            loss += s_sum[0] + s_sum[1] + s_sum[2] + s_sum[3]
                  + s_sum[4] + s_sum[5] + s_sum[6] + s_sum[7];
            // ---- refill this stage with row r+STAGES ----
            const int nr = r + STAGES;
            if (nr < ROWS_PB) {
                const int gr = row0 + nr;
                const unsigned mbs = su32(&mbar[s]);
                asm volatile("mbarrier.arrive.expect_tx.shared.b64 _, [%0], %1;"
                             :: "r"(mbs), "r"(2 * ROW_BYTES) : "memory");
                bulk_ldg(su32(buf[s]),             target + (size_t)gr * C_CLASSES, mbs);
                bulk_ldg(su32(buf[s]) + ROW_BYTES, logits + (size_t)gr * C_CLASSES, mbs);
            }
        }
    }

    if (t == 0)
        atomicAdd(out, loss * inv_B);
}

extern "C" void kernel_launch(void* const* d_in, const int* in_sizes, int n_in,
                              void* d_out, int out_size) {
    const float* logits = (const float*)d_in[0];
    const float* target = (const float*)d_in[1];
    float* out = (float*)d_out;

    const int B = in_sizes[0] / C_CLASSES;   // 16384

    cudaMemsetAsync(out, 0, sizeof(float));
    ranking_loss_kernel<<<B / ROWS_PB, THREADS>>>(logits, target, out, 1.0f / (float)B);
}

// round 9
// speedup vs baseline: 1.2276x; 1.0285x over previous
#include <cuda_runtime.h>
#include <cstdint>

// RankingLoss: B=16384 rows, C=1000 classes.
// cp.async.bulk staged ring (4 stages x [tgt|lgt] row), 1 barrier per row,
// per-thread loss accumulation across rows, single final block reduction,
// device-scratch global accumulation (no separate memset launch).

#define C_CLASSES 1000
#define C4        250
#define ROW_BYTES 4000
#define STAGES    4
#define ROWS_PB   8
#define THREADS   256

__device__ float    g_scratch;   // zero-init at module load; reset by last block
__device__ unsigned g_count;

__device__ __forceinline__ unsigned su32(const void* p) {
    return (unsigned)__cvta_generic_to_shared(p);
}

__device__ __forceinline__ void bulk_ldg(unsigned dst, const void* src, unsigned mbar) {
    asm volatile(
        "cp.async.bulk.shared::cta.global.mbarrier::complete_tx::bytes [%0], [%1], %2, [%3];"
        :: "r"(dst), "l"(src), "r"(ROW_BYTES), "r"(mbar) : "memory");
}

__device__ __forceinline__ void mbar_wait(unsigned mbar, unsigned phase) {
    unsigned done;
    asm volatile(
        "{\n\t.reg .pred p;\n\t"
        "mbarrier.try_wait.parity.acquire.cta.shared::cta.b64 p, [%1], %2, 0x989680;\n\t"
        "selp.b32 %0, 1, 0, p;\n\t}"
        : "=r"(done) : "r"(mbar), "r"(phase) : "memory");
    while (!done) {
        asm volatile(
            "{\n\t.reg .pred p;\n\t"
            "mbarrier.try_wait.parity.acquire.cta.shared::cta.b64 p, [%1], %2, 0x989680;\n\t"
            "selp.b32 %0, 1, 0, p;\n\t}"
            : "=r"(done) : "r"(mbar), "r"(phase) : "memory");
    }
}

__global__ __launch_bounds__(THREADS)
void ranking_loss_kernel(const float* __restrict__ logits,
                         const float* __restrict__ target,
                         float* __restrict__ out,
                         float inv_B) {
    __shared__ alignas(16) char buf[STAGES][2 * ROW_BYTES];
    __shared__ alignas(8) unsigned long long mbar[STAGES];
    __shared__ unsigned s_mb[2][8], s_mi[2][8];   // double-buffered by row parity
    __shared__ float    s_lx[2][8];
    __shared__ float    s_sum[8];

    const int t    = threadIdx.x;
    const int lane = t & 31;
    const int warp = t >> 5;
    const int row0 = blockIdx.x * ROWS_PB;
    const bool act = (t < C4);
    const unsigned full = 0xffffffffu;

    if (t == 0) {
        #pragma unroll
        for (int s = 0; s < STAGES; s++)
            asm volatile("mbarrier.init.shared.b64 [%0], 1;"
                         :: "r"(su32(&mbar[s])) : "memory");
    }
    __syncthreads();

    // ---- prologue: fill all stages ----
    if (t == 0) {
        #pragma unroll
        for (int s = 0; s < STAGES; s++) {
            const int r = row0 + s;
            const unsigned mb = su32(&mbar[s]);
            asm volatile("mbarrier.arrive.expect_tx.shared.b64 _, [%0], %1;"
                         :: "r"(mb), "r"(2 * ROW_BYTES) : "memory");
            bulk_ldg(su32(buf[s]),             target + (size_t)r * C_CLASSES, mb);
            bulk_ldg(su32(buf[s]) + ROW_BYTES, logits + (size_t)r * C_CLASSES, mb);
        }
    }

    float loss = 0.f;   // per-thread accumulator across all rows

    for (int r = 0; r < ROWS_PB; r++) {
        const int s = r & (STAGES - 1);
        const int p = r & 1;
        const unsigned phase = (unsigned)(r / STAGES) & 1u;

        mbar_wait(su32(&mbar[s]), phase);

        // ---- consume this thread's vec4s from smem ----
        const float4* tv4 = reinterpret_cast<const float4*>(buf[s]);
        const float4* lv4 = reinterpret_cast<const float4*>(buf[s] + ROW_BYTES);
        float4 tv = make_float4(0.f, 0.f, 0.f, 0.f);             // pad < any real target
        float4 lv = make_float4(-1e30f, -1e30f, -1e30f, -1e30f); // pad: relu -> 0
        if (act) { tv = tv4[t]; lv = lv4[t]; }

        // ---- local argmax (first-index ties), carrying the paired logit ----
        const int base = 4 * t;
        float m = tv.x; int mi = base; float mlx = lv.x;
        if (tv.y > m) { m = tv.y; mi = base + 1; mlx = lv.y; }
        if (tv.z > m) { m = tv.z; mi = base + 2; mlx = lv.z; }
        if (tv.w > m) { m = tv.w; mi = base + 3; mlx = lv.w; }

        // warp argmax via REDUX (targets >= 0: positive-float bits order-preserving)
        const unsigned mb   = __float_as_uint(m);
        const unsigned wmb  = __reduce_max_sync(full, mb);
        const unsigned cand = (mb == wmb) ? (unsigned)mi : 0xffffffffu;
        const unsigned wmi  = __reduce_min_sync(full, cand);

        if (mb == wmb && (unsigned)mi == wmi) s_lx[p][warp] = mlx;  // unique owner
        if (lane == 0) { s_mb[p][warp] = wmb; s_mi[p][warp] = wmi; }
        __syncthreads();   // ONE barrier per row: publishes winners; buf[s] fully read

        // ---- refill this stage right away (reads completed before the barrier) ----
        if (t == 0) {
            const int nr = r + STAGES;
            if (nr < ROWS_PB) {
                const int gr = row0 + nr;
                const unsigned mbs = su32(&mbar[s]);
                asm volatile("mbarrier.arrive.expect_tx.shared.b64 _, [%0], %1;"
                             :: "r"(mbs), "r"(2 * ROW_BYTES) : "memory");
                bulk_ldg(su32(buf[s]),             target + (size_t)gr * C_CLASSES, mbs);
                bulk_ldg(su32(buf[s]) + ROW_BYTES, logits + (size_t)gr * C_CLASSES, mbs);
            }
        }

        // ---- combine 8 warp winners via REDUX (lanes 0-7 hold them) ----
        const unsigned v  = (lane < 8) ? s_mb[p][lane] : 0u;
        const unsigned wv = __reduce_max_sync(full, v);
        const unsigned c2 = (v == wv && lane < 8) ? s_mi[p][lane] : 0xffffffffu;
        const unsigned bi = __reduce_min_sync(full, c2);        // block argmax index
        const unsigned own = __ballot_sync(full, c2 == bi);     // unique (disjoint mi ranges)
        const float x1 = __shfl_sync(full, (lane < 8) ? s_lx[p][lane] : 0.f,
                                     __ffs(own) - 1);
        const int label = (int)bi;

        // ---- margin-relu accumulation (no per-row reduction) ----
        if (label != 0) {
            const float inv_pos = 1.0f / (float)(C_CLASSES - 1);
            const float flabel  = (float)label;
            const float nx1     = -x1;
            const float la[4]   = {lv.x, lv.y, lv.z, lv.w};
            const float fb      = (float)base;
            #pragma unroll
            for (int k = 0; k < 4; k++) {
                // j==0 only at t==0,k==0: margin = 1.0 (NEG_MARGIN * relu term)
                const float margin = (t == 0 && k == 0)
                                   ? 1.0f
                                   : fabsf(flabel - (fb + (float)k)) * inv_pos;
                loss += fmaxf(0.f, la[k] + nx1 + margin);
            }
        }
    }

    // ---- single block reduction at the end ----
    #pragma unroll
    for (int off = 16; off > 0; off >>= 1)
        loss += __shfl_down_sync(full, loss, off);
    if (lane == 0) s_sum[warp] = loss;
    __syncthreads();

    if (t == 0) {
        const float total = s_sum[0] + s_sum[1] + s_sum[2] + s_sum[3]
                          + s_sum[4] + s_sum[5] + s_sum[6] + s_sum[7];
        atomicAdd(&g_scratch, total);
        __threadfence();
        const unsigned done = atomicAdd(&g_count, 1u);
        if (done == gridDim.x - 1) {                 // last block finalizes
            __threadfence();
            const float acc = *((volatile float*)&g_scratch);
            out[0] = acc * inv_B;
            // reset for the next (graph-replayed) launch
            g_scratch = 0.f;
            g_count   = 0u;
            __threadfence();
        }
    }
}

extern "C" void kernel_launch(void* const* d_in, const int* in_sizes, int n_in,
                              void* d_out, int out_size) {
    const float* logits = (const float*)d_in[0];
    const float* target = (const float*)d_in[1];
    float* out = (float*)d_out;

    const int B = in_sizes[0] / C_CLASSES;   // 16384

    ranking_loss_kernel<<<B / ROWS_PB, THREADS>>>(logits, target, out, 1.0f / (float)B);
}

// round 12
// speedup vs baseline: 1.3246x; 1.0789x over previous
#include <cuda_runtime.h>
#include <cstdint>

// RankingLoss: B=16384 rows, C=1000 classes.
// Warp-autonomous TMA pipelines: each warp owns a private 2-slot smem ring +
// mbarriers, streams RPW rows, reduces each row entirely within the warp
// (REDUX argmax + margin sum). No __syncthreads in the main loop.

#define C_CLASSES 1000
#define C4        250
#define ROW_BYTES 4000
#define SLOT_BYTES 8192          // [tgt 4000 | lgt 4000] padded
#define SLOTS     2
#define WARPS     4
#define THREADS   (WARPS * 32)
#define RPW       4              // rows per warp
#define VS        8              // vec4 slots per lane (ceil(250/32))

__device__ float    g_scratch;   // zero-init at module load; reset by last block
__device__ unsigned g_count;

__device__ __forceinline__ unsigned su32(const void* p) {
    return (unsigned)__cvta_generic_to_shared(p);
}

__device__ __forceinline__ void bulk_ldg(unsigned dst, const void* src, unsigned mbar) {
    asm volatile(
        "cp.async.bulk.shared::cta.global.mbarrier::complete_tx::bytes [%0], [%1], %2, [%3];"
        :: "r"(dst), "l"(src), "r"(ROW_BYTES), "r"(mbar) : "memory");
}

__device__ __forceinline__ void mbar_wait(unsigned mbar, unsigned phase) {
    unsigned done;
    asm volatile(
        "{\n\t.reg .pred p;\n\t"
        "mbarrier.try_wait.parity.acquire.cta.shared::cta.b64 p, [%1], %2, 0x989680;\n\t"
        "selp.b32 %0, 1, 0, p;\n\t}"
        : "=r"(done) : "r"(mbar), "r"(phase) : "memory");
    while (!done) {
        asm volatile(
            "{\n\t.reg .pred p;\n\t"
            "mbarrier.try_wait.parity.acquire.cta.shared::cta.b64 p, [%1], %2, 0x989680;\n\t"
            "selp.b32 %0, 1, 0, p;\n\t}"
            : "=r"(done) : "r"(mbar), "r"(phase) : "memory");
    }
}

__global__ __launch_bounds__(THREADS)
void ranking_loss_kernel(const float* __restrict__ logits,
                         const float* __restrict__ target,
                         float* __restrict__ out,
                         float inv_B) {
    __shared__ alignas(128) char buf[WARPS][SLOTS][SLOT_BYTES];
    __shared__ alignas(8) unsigned long long mbar[WARPS][SLOTS];
    __shared__ float s_sum[WARPS];

    const int lane = threadIdx.x & 31;
    const int warp = threadIdx.x >> 5;
    const unsigned full = 0xffffffffu;

    const int wrow0 = (blockIdx.x * WARPS + warp) * RPW;  // this warp's first row

    // ---- per-warp mbarrier init + prologue fill (lane 0 only; private state) ----
    if (lane == 0) {
        #pragma unroll
        for (int s = 0; s < SLOTS; s++)
            asm volatile("mbarrier.init.shared.b64 [%0], 1;"
                         :: "r"(su32(&mbar[warp][s])) : "memory");
        // order init before the TMA engine observes the barriers
        asm volatile("fence.proxy.async.shared::cta;" ::: "memory");
        #pragma unroll
        for (int s = 0; s < SLOTS; s++) {
            const int r = wrow0 + s;
            const unsigned mb = su32(&mbar[warp][s]);
            asm volatile("mbarrier.arrive.expect_tx.shared.b64 _, [%0], %1;"
                         :: "r"(mb), "r"(2 * ROW_BYTES) : "memory");
            bulk_ldg(su32(buf[warp][s]),             target + (size_t)r * C_CLASSES, mb);
            bulk_ldg(su32(buf[warp][s]) + ROW_BYTES, logits + (size_t)r * C_CLASSES, mb);
        }
    }

    float loss = 0.f;

    for (int i = 0; i < RPW; i++) {
        const int slot = i & (SLOTS - 1);
        const unsigned phase = (unsigned)(i / SLOTS) & 1u;

        mbar_wait(su32(&mbar[warp][slot]), phase);

        const float4* tg4 = reinterpret_cast<const float4*>(buf[warp][slot]);
        const float4* lg4 = reinterpret_cast<const float4*>(buf[warp][slot] + ROW_BYTES);

        // ---- pass 1: warp argmax over targets, carrying the paired logit ----
        // slot v = s*32+lane; v<250 valid. s=0 valid for every lane.
        float m   = -1.f;                 // below any uniform[0,1) target
        int   mi  = 0x7fffffff;
        float mlx = 0.f;
        #pragma unroll
        for (int s = 0; s < VS; s++) {
            const int v = s * 32 + lane;
            if (v < C4) {
                const float4 tvv = tg4[v];
                const float4 lvv = lg4[v];
                const int base = 4 * v;
                const float ta[4] = {tvv.x, tvv.y, tvv.z, tvv.w};
                const float la[4] = {lvv.x, lvv.y, lvv.z, lvv.w};
                #pragma unroll
                for (int k = 0; k < 4; k++)      // ascending index: strict > keeps first
                    if (ta[k] > m) { m = ta[k]; mi = base + k; mlx = la[k]; }
            }
        }

        // targets >= 0: positive-float bits order-preserving as u32
        const unsigned mb   = __float_as_uint(m);
        const unsigned wmb  = __reduce_max_sync(full, mb);
        const unsigned cand = (mb == wmb) ? (unsigned)mi : 0xffffffffu;
        const unsigned wmi  = __reduce_min_sync(full, cand);     // first-index tiebreak
        const unsigned own  = __ballot_sync(full, (mb == wmb) & ((unsigned)mi == wmi));
        const float x1      = __shfl_sync(full, mlx, __ffs(own) - 1);
        const int label     = (int)wmi;

        // ---- pass 2: margin-relu sum (re-read logits from smem) ----
        if (label != 0) {
            const float inv_pos = 1.0f / (float)(C_CLASSES - 1);
            const float flabel  = (float)label;
            const float nx1     = -x1;
            #pragma unroll
            for (int s = 0; s < VS; s++) {
                const int v = s * 32 + lane;
                if (v < C4) {
                    const float4 lvv = lg4[v];
                    const float la[4] = {lvv.x, lvv.y, lvv.z, lvv.w};
                    const float fb = (float)(4 * v);
                    #pragma unroll
                    for (int k = 0; k < 4; k++) {
                        // j==0 only at v==0,k==0 (lane 0): margin = 1.0
                        const float margin = (v == 0 && k == 0)
                                           ? 1.0f
                                           : fabsf(flabel - (fb + (float)k)) * inv_pos;
                        loss += fmaxf(0.f, la[k] + nx1 + margin);
                    }
                }
            }
        }

        // ---- refill this slot with row i+SLOTS (all lanes done reading it) ----
        __syncwarp();
        if (lane == 0 && i + SLOTS < RPW) {
            asm volatile("fence.proxy.async.shared::cta;" ::: "memory");
            const int gr = wrow0 + i + SLOTS;
            const unsigned mbs = su32(&mbar[warp][slot]);
            asm volatile("mbarrier.arrive.expect_tx.shared.b64 _, [%0], %1;"
                         :: "r"(mbs), "r"(2 * ROW_BYTES) : "memory");
            bulk_ldg(su32(buf[warp][slot]),             target + (size_t)gr * C_CLASSES, mbs);
            bulk_ldg(su32(buf[warp][slot]) + ROW_BYTES, logits + (size_t)gr * C_CLASSES, mbs);
        }
    }

    // ---- warp sum, block combine, global accumulate ----
    #pragma unroll
    for (int off = 16; off > 0; off >>= 1)
        loss += __shfl_down_sync(full, loss, off);
    if (lane == 0) s_sum[warp] = loss;
    __syncthreads();

    if (threadIdx.x == 0) {
        const float total = s_sum[0] + s_sum[1] + s_sum[2] + s_sum[3];
        atomicAdd(&g_scratch, total);
        __threadfence();
        const unsigned done = atomicAdd(&g_count, 1u);
        if (done == gridDim.x - 1) {                 // last block finalizes
            __threadfence();
            const float acc = *((volatile float*)&g_scratch);
            out[0] = acc * inv_B;
            g_scratch = 0.f;                         // reset for next graph replay
            g_count   = 0u;
            __threadfence();
        }
    }
}

extern "C" void kernel_launch(void* const* d_in, const int* in_sizes, int n_in,
                              void* d_out, int out_size) {
    const float* logits = (const float*)d_in[0];
    const float* target = (const float*)d_in[1];
    float* out = (float*)d_out;

    const int B = in_sizes[0] / C_CLASSES;           // 16384
    const int grid = B / (WARPS * RPW);              // 1024

    ranking_loss_kernel<<<grid, THREADS>>>(logits, target, out, 1.0f / (float)B);
}

// round 13
// speedup vs baseline: 1.3790x; 1.0411x over previous
#include <cuda_runtime.h>
#include <cstdint>

// RankingLoss: B=16384 rows, C=1000 classes.
// Persistent single-wave kernel: grid = 304 CTAs (2/SM on 152-SM GB300), all
// resident simultaneously. Warp-autonomous 3-slot TMA rings; rows assigned by
// global-warp striding. No __syncthreads in the main loop.

#define C_CLASSES 1000
#define C4        250
#define ROW_BYTES 4000
#define SLOT_BYTES 8192          // [tgt 4000 | lgt 4000] padded
#define SLOTS     3
#define WARPS     4
#define THREADS   (WARPS * 32)
#define GRID      304
#define NWARPS    (GRID * WARPS)   // 1216
#define VS        8                // vec4 slots per lane (ceil(250/32))

__device__ float    g_scratch;   // zero-init at module load; reset by last block
__device__ unsigned g_count;

__device__ __forceinline__ unsigned su32(const void* p) {
    return (unsigned)__cvta_generic_to_shared(p);
}

__device__ __forceinline__ void bulk_ldg(unsigned dst, const void* src, unsigned mbar) {
    asm volatile(
        "cp.async.bulk.shared::cta.global.mbarrier::complete_tx::bytes [%0], [%1], %2, [%3];"
        :: "r"(dst), "l"(src), "r"(ROW_BYTES), "r"(mbar) : "memory");
}

__device__ __forceinline__ void mbar_wait(unsigned mbar, unsigned phase) {
    unsigned done;
    asm volatile(
        "{\n\t.reg .pred p;\n\t"
        "mbarrier.try_wait.parity.acquire.cta.shared::cta.b64 p, [%1], %2, 0x989680;\n\t"
        "selp.b32 %0, 1, 0, p;\n\t}"
        : "=r"(done) : "r"(mbar), "r"(phase) : "memory");
    while (!done) {
        asm volatile(
            "{\n\t.reg .pred p;\n\t"
            "mbarrier.try_wait.parity.acquire.cta.shared::cta.b64 p, [%1], %2, 0x989680;\n\t"
            "selp.b32 %0, 1, 0, p;\n\t}"
            : "=r"(done) : "r"(mbar), "r"(phase) : "memory");
    }
}

extern __shared__ char dynbuf[];   // [WARPS][SLOTS][SLOT_BYTES]

__global__ __launch_bounds__(THREADS)
void ranking_loss_kernel(const float* __restrict__ logits,
                         const float* __restrict__ target,
                         float* __restrict__ out,
                         float inv_B, int B) {
    __shared__ alignas(8) unsigned long long mbar[WARPS][SLOTS];
    __shared__ float s_sum[WARPS];

    const int lane = threadIdx.x & 31;
    const int warp = threadIdx.x >> 5;
    const unsigned full = 0xffffffffu;

    const int g = blockIdx.x * WARPS + warp;      // global warp id, rows g, g+NWARPS, ...
    char* wbuf = dynbuf + (size_t)warp * SLOTS * SLOT_BYTES;

    // ---- per-warp mbarrier init + prologue fill (lane 0; private state) ----
    if (lane == 0) {
        #pragma unroll
        for (int s = 0; s < SLOTS; s++)
            asm volatile("mbarrier.init.shared.b64 [%0], 1;"
                         :: "r"(su32(&mbar[warp][s])) : "memory");
        asm volatile("fence.proxy.async.shared::cta;" ::: "memory");
        #pragma unroll
        for (int s = 0; s < SLOTS; s++) {
            const int r = g + s * NWARPS;         // always < B (g <= 1215, +2*1216 < 16384)
            const unsigned mb = su32(&mbar[warp][s]);
            asm volatile("mbarrier.arrive.expect_tx.shared.b64 _, [%0], %1;"
                         :: "r"(mb), "r"(2 * ROW_BYTES) : "memory");
            bulk_ldg(su32(wbuf + s * SLOT_BYTES),             target + (size_t)r * C_CLASSES, mb);
            bulk_ldg(su32(wbuf + s * SLOT_BYTES) + ROW_BYTES, logits + (size_t)r * C_CLASSES, mb);
        }
    }

    float loss = 0.f;
    int slot = 0, phase = 0;

    for (int r = g; r < B; r += NWARPS) {
        mbar_wait(su32(&mbar[warp][slot]), (unsigned)phase);

        const char* sb = wbuf + slot * SLOT_BYTES;
        const float4* tg4 = reinterpret_cast<const float4*>(sb);
        const float4* lg4 = reinterpret_cast<const float4*>(sb + ROW_BYTES);

        // ---- pass 1: warp argmax over targets, carrying the paired logit ----
        float m   = -1.f;                 // below any uniform[0,1) target
        int   mi  = 0x7fffffff;
        float mlx = 0.f;
        #pragma unroll
        for (int s = 0; s < VS; s++) {
            const int v = s * 32 + lane;
            if (v < C4) {
                const float4 tvv = tg4[v];
                const float4 lvv = lg4[v];
                const int base = 4 * v;
                const float ta[4] = {tvv.x, tvv.y, tvv.z, tvv.w};
                const float la[4] = {lvv.x, lvv.y, lvv.z, lvv.w};
                #pragma unroll
                for (int k = 0; k < 4; k++)      // ascending index: strict > keeps first
                    if (ta[k] > m) { m = ta[k]; mi = base + k; mlx = la[k]; }
            }
        }

        // targets >= 0: positive-float bits order-preserving as u32
        const unsigned mb   = __float_as_uint(m);
        const unsigned wmb  = __reduce_max_sync(full, mb);
        const unsigned cand = (mb == wmb) ? (unsigned)mi : 0xffffffffu;
        const unsigned wmi  = __reduce_min_sync(full, cand);     // first-index tiebreak
        const unsigned own  = __ballot_sync(full, (mb == wmb) & ((unsigned)mi == wmi));
        const float x1      = __shfl_sync(full, mlx, __ffs(own) - 1);
        const int label     = (int)wmi;

        // ---- pass 2: margin-relu sum (re-read logits from smem) ----
        if (label != 0) {
            const float inv_pos = 1.0f / (float)(C_CLASSES - 1);
            const float flabel  = (float)label;
            const float nx1     = -x1;
            #pragma unroll
            for (int s = 0; s < VS; s++) {
                const int v = s * 32 + lane;
                if (v < C4) {
                    const float4 lvv = lg4[v];
                    const float la[4] = {lvv.x, lvv.y, lvv.z, lvv.w};
                    const float fb = (float)(4 * v);
                    #pragma unroll
                    for (int k = 0; k < 4; k++) {
                        // j==0 only at v==0,k==0 (lane 0): margin = 1.0
                        const float margin = (v == 0 && k == 0)
                                           ? 1.0f
                                           : fabsf(flabel - (fb + (float)k)) * inv_pos;
                        loss += fmaxf(0.f, la[k] + nx1 + margin);
                    }
                }
            }
        }

        // ---- refill this slot with row r + SLOTS*NWARPS ----
        __syncwarp();
        const int rr = r + SLOTS * NWARPS;
        if (lane == 0 && rr < B) {
            asm volatile("fence.proxy.async.shared::cta;" ::: "memory");
            const unsigned mbs = su32(&mbar[warp][slot]);
            asm volatile("mbarrier.arrive.expect_tx.shared.b64 _, [%0], %1;"
                         :: "r"(mbs), "r"(2 * ROW_BYTES) : "memory");
            bulk_ldg(su32((char*)sb),             target + (size_t)rr * C_CLASSES, mbs);
            bulk_ldg(su32((char*)sb) + ROW_BYTES, logits + (size_t)rr * C_CLASSES, mbs);
        }

        if (++slot == SLOTS) { slot = 0; phase ^= 1; }
    }

    // ---- warp sum, block combine, global accumulate ----
    #pragma unroll
    for (int off = 16; off > 0; off >>= 1)
        loss += __shfl_down_sync(full, loss, off);
    if (lane == 0) s_sum[warp] = loss;
    __syncthreads();

    if (threadIdx.x == 0) {
        const float total = s_sum[0] + s_sum[1] + s_sum[2] + s_sum[3];
        atomicAdd(&g_scratch, total);
        __threadfence();
        const unsigned done = atomicAdd(&g_count, 1u);
        if (done == gridDim.x - 1) {                 // last block finalizes
            __threadfence();
            const float acc = *((volatile float*)&g_scratch);
            out[0] = acc * inv_B;
            g_scratch = 0.f;                         // reset for next graph replay
            g_count   = 0u;
            __threadfence();
        }
    }
}

extern "C" void kernel_launch(void* const* d_in, const int* in_sizes, int n_in,
                              void* d_out, int out_size) {
    const float* logits = (const float*)d_in[0];
    const float* target = (const float*)d_in[1];
    float* out = (float*)d_out;

    const int B = in_sizes[0] / C_CLASSES;           // 16384
    const int smem = WARPS * SLOTS * SLOT_BYTES;     // 98304

    cudaFuncSetAttribute(ranking_loss_kernel,
                         cudaFuncAttributeMaxDynamicSharedMemorySize, smem);
    ranking_loss_kernel<<<GRID, THREADS, smem>>>(logits, target, out,
                                                 1.0f / (float)B, B);
}